// round 11
// baseline (speedup 1.0000x reference)
#include <cuda_runtime.h>

// Depthwise 1D cross-correlation, 13-tap kernel shared across 16384 rows of L=4096 fp32.
// out[r,l] = sum_j kern[j]*x[r, l+j-6], zero-padded; kern[j] = w[6-j] (j<7) else w[j].
//
// R4: one aligned LDG.128 per thread; neighbor blocks obtained via warp shuffle
// (register-file exchange) instead of overlapping global loads. Cuts L1 read
// wavefronts per warp from 20 -> ~8. Lanes 0,1,30,31 patch via predicated loads,
// which also implement the zero-padding at row boundaries.

#define TAPS 13
#define LVAL 4096
#define THREADS 256

__global__ __launch_bounds__(THREADS)
void dwconv13_kernel(const float* __restrict__ x,
                     const float* __restrict__ w,
                     float* __restrict__ out)
{
    const unsigned FULL = 0xffffffffu;
    const int g    = blockIdx.x * THREADS + threadIdx.x;
    const int lane = threadIdx.x & 31;
    const long long oFlat = (long long)g * 4;
    const int col = (int)(oFlat & (LVAL - 1));   // start column within row
    const long long rowBase = oFlat - col;
    const float* p = x + oFlat;                  // &x[row, col], 16B aligned

    // Taps, flipped: kern[j] = w[6-j] (j<7), w[j] (j>=7).
    float4 w0 = *reinterpret_cast<const float4*>(w + 0);
    float4 w1 = *reinterpret_cast<const float4*>(w + 4);
    float4 w2 = *reinterpret_cast<const float4*>(w + 8);
    float  w12 = __ldg(w + 12);
    float kern[TAPS];
    kern[0] = w1.z;  kern[1] = w1.y;  kern[2] = w1.x;  kern[3] = w0.w;
    kern[4] = w0.z;  kern[5] = w0.y;  kern[6] = w0.x;
    kern[7] = w1.w;  kern[8] = w2.x;  kern[9] = w2.y;  kern[10] = w2.z;
    kern[11] = w2.w; kern[12] = w12;

    // Own block: cols col..col+3 (always fully in-bounds; L % 128 == 0).
    float4 c = *reinterpret_cast<const float4*>(p);

    // Neighbor blocks from adjacent lanes (warp chunk = 128 consecutive cols).
    float4 b, d;                 // blocks col-4, col+4
    float az, aw, ex, ey;        // block col-8 (.z,.w), block col+8 (.x,.y)
    b.x = __shfl_up_sync(FULL, c.x, 1);
    b.y = __shfl_up_sync(FULL, c.y, 1);
    b.z = __shfl_up_sync(FULL, c.z, 1);
    b.w = __shfl_up_sync(FULL, c.w, 1);
    az  = __shfl_up_sync(FULL, c.z, 2);
    aw  = __shfl_up_sync(FULL, c.w, 2);
    d.x = __shfl_down_sync(FULL, c.x, 1);
    d.y = __shfl_down_sync(FULL, c.y, 1);
    d.z = __shfl_down_sync(FULL, c.z, 1);
    d.w = __shfl_down_sync(FULL, c.w, 1);
    ex  = __shfl_down_sync(FULL, c.x, 2);
    ey  = __shfl_down_sync(FULL, c.y, 2);

    // Edge-lane patch-up (also provides zero padding at row boundaries).
    if (lane == 0) {
        if (col >= 4) b = *reinterpret_cast<const float4*>(p - 4);
        else          b = make_float4(0.f, 0.f, 0.f, 0.f);
        if (col >= 8) { float4 t = *reinterpret_cast<const float4*>(p - 8); az = t.z; aw = t.w; }
        else          { az = 0.f; aw = 0.f; }
    }
    if (lane == 1) {
        if (col >= 8) { float4 t = *reinterpret_cast<const float4*>(p - 8); az = t.z; aw = t.w; }
        else          { az = 0.f; aw = 0.f; }
    }
    if (lane == 30) {
        if (col + 8 < LVAL) { float4 t = *reinterpret_cast<const float4*>(p + 8); ex = t.x; ey = t.y; }
        else                { ex = 0.f; ey = 0.f; }
    }
    if (lane == 31) {
        if (col + 4 < LVAL) d = *reinterpret_cast<const float4*>(p + 4);
        else                d = make_float4(0.f, 0.f, 0.f, 0.f);
        if (col + 8 < LVAL) { float4 t = *reinterpret_cast<const float4*>(p + 8); ex = t.x; ey = t.y; }
        else                { ex = 0.f; ey = 0.f; }
    }

    // v[t] = x[row, col-6+t], t=0..15
    float v[16];
    v[0]=az;   v[1]=aw;
    v[2]=b.x;  v[3]=b.y;  v[4]=b.z;  v[5]=b.w;
    v[6]=c.x;  v[7]=c.y;  v[8]=c.z;  v[9]=c.w;
    v[10]=d.x; v[11]=d.y; v[12]=d.z; v[13]=d.w;
    v[14]=ex;  v[15]=ey;

    float acc0 = 0.f, acc1 = 0.f, acc2 = 0.f, acc3 = 0.f;
    #pragma unroll
    for (int j = 0; j < TAPS; j++) {
        float kj = kern[j];
        acc0 = fmaf(kj, v[j + 0], acc0);
        acc1 = fmaf(kj, v[j + 1], acc1);
        acc2 = fmaf(kj, v[j + 2], acc2);
        acc3 = fmaf(kj, v[j + 3], acc3);
    }

    *reinterpret_cast<float4*>(out + oFlat) = make_float4(acc0, acc1, acc2, acc3);
    (void)rowBase;
}

extern "C" void kernel_launch(void* const* d_in, const int* in_sizes, int n_in,
                              void* d_out, int out_size)
{
    const float* x = (const float*)d_in[0];
    const float* w = (const float*)d_in[1];
    float* out     = (float*)d_out;

    const int n = in_sizes[0];                 // 16384 * 4096
    const int nThreadsTotal = n / 4;
    dwconv13_kernel<<<nThreadsTotal / THREADS, THREADS>>>(x, w, out);
}

// round 12
// speedup vs baseline: 1.0409x; 1.0409x over previous
#include <cuda_runtime.h>

// Depthwise 1D cross-correlation, 13-tap kernel shared across 16384 rows of L=4096 fp32.
// out[r,l] = sum_j kern[j]*x[r, l+j-6], zero-padded; kern[j] = w[6-j] (j<7) else w[j].
//
// R5: 16 outputs per thread. Window (28 floats) covered by 8 aligned LDG.128;
// read redundancy drops 5x -> 2x, L1 wavefronts per 128 outputs drop 24 -> 12.
// No smem, no shuffle. Only cols 0 and 4080 of each row take the slow path.

#define TAPS 13
#define LVAL 4096
#define THREADS 256
#define OPT 16          // outputs per thread

__global__ __launch_bounds__(THREADS)
void dwconv13_kernel(const float* __restrict__ x,
                     const float* __restrict__ w,
                     float* __restrict__ out)
{
    const int g = blockIdx.x * THREADS + threadIdx.x;
    const long long oFlat = (long long)g * OPT;
    const int col = (int)(oFlat & (LVAL - 1));     // start column within row (mult of 16)
    const long long rowBase = oFlat - col;
    const float* p = x + oFlat;                    // &x[row, col], 16B aligned

    // Taps, flipped: kern[j] = w[6-j] (j<7), w[j] (j>=7).
    float4 w0 = *reinterpret_cast<const float4*>(w + 0);
    float4 w1 = *reinterpret_cast<const float4*>(w + 4);
    float4 w2 = *reinterpret_cast<const float4*>(w + 8);
    float  w12 = __ldg(w + 12);
    float kern[TAPS];
    kern[0] = w1.z;  kern[1] = w1.y;  kern[2] = w1.x;  kern[3] = w0.w;
    kern[4] = w0.z;  kern[5] = w0.y;  kern[6] = w0.x;
    kern[7] = w1.w;  kern[8] = w2.x;  kern[9] = w2.y;  kern[10] = w2.z;
    kern[11] = w2.w; kern[12] = w12;

    // v[t] = x[row, col - 8 + t], t = 0..31 (zero outside row).
    // Window needed: cols col-6 .. col+21  ->  v[2..29].
    float v[32];

    if (col >= 16 && col <= LVAL - 32) {
        // Fast path: 8 aligned float4 loads, fully in-bounds (254/256 threads per row).
        #pragma unroll
        for (int blk = 0; blk < 8; blk++) {
            float4 t = *reinterpret_cast<const float4*>(p + (blk * 4 - 8));
            v[blk * 4 + 0] = t.x;
            v[blk * 4 + 1] = t.y;
            v[blk * 4 + 2] = t.z;
            v[blk * 4 + 3] = t.w;
        }
    } else {
        // Row-edge path (col == 0 or col == 4080): bounds-checked scalars.
        #pragma unroll
        for (int t = 0; t < 32; t++) {
            int cc = col - 8 + t;
            v[t] = (cc >= 0 && cc < LVAL) ? __ldg(x + rowBase + cc) : 0.0f;
        }
    }

    // acc[i] = sum_j kern[j] * v[i + 2 + j],  i = 0..15
    float acc[OPT];
    #pragma unroll
    for (int i = 0; i < OPT; i++) acc[i] = 0.0f;

    #pragma unroll
    for (int j = 0; j < TAPS; j++) {
        float kj = kern[j];
        #pragma unroll
        for (int i = 0; i < OPT; i++)
            acc[i] = fmaf(kj, v[i + 2 + j], acc[i]);
    }

    float* po = out + oFlat;
    #pragma unroll
    for (int q = 0; q < OPT / 4; q++) {
        *reinterpret_cast<float4*>(po + q * 4) =
            make_float4(acc[q * 4 + 0], acc[q * 4 + 1], acc[q * 4 + 2], acc[q * 4 + 3]);
    }
}

extern "C" void kernel_launch(void* const* d_in, const int* in_sizes, int n_in,
                              void* d_out, int out_size)
{
    const float* x = (const float*)d_in[0];
    const float* w = (const float*)d_in[1];
    float* out     = (float*)d_out;

    const int n = in_sizes[0];                  // 16384 * 4096
    const int nThreadsTotal = n / OPT;
    dwconv13_kernel<<<nThreadsTotal / THREADS, THREADS>>>(x, w, out);
}

// round 13
// speedup vs baseline: 1.1894x; 1.1427x over previous
#include <cuda_runtime.h>

// Depthwise 1D cross-correlation, 13-tap kernel shared across 16384 rows of L=4096 fp32.
// out[r,l] = sum_j kern[j]*x[r, l+j-6], zero-padded; kern[j] = w[6-j] (j<7) else w[j].
//
// R6: shifted-window gather. Thread at quad `col` loads EXACTLY 4 aligned float4
// blocks (cols col-4..col+11) and computes outputs col+2..col+5. The 2-left-shift
// is fixed by shuffling acc2,acc3 down one lane so stores stay aligned STG.128.
// Lane 0 of each 128-chunk self-computes its two leftmost outputs.
// L1 wavefronts per 128 outputs: 16 read + 4 store (+eps) vs 24 in R3.

#define TAPS 13
#define LVAL 4096
#define THREADS 256

template<bool EDGE_LEFT, bool EDGE_RIGHT>
__device__ __forceinline__ void do_quad(const float* __restrict__ x,
                                        float* __restrict__ out,
                                        long long rowBase, int col, int lane,
                                        const float kern[TAPS])
{
    const unsigned FULL = 0xffffffffu;
    const float* p = x + rowBase + col;
    const float4 Z = make_float4(0.f, 0.f, 0.f, 0.f);

    // Blocks covering cols col-4 .. col+11 (predicates only on the edge-capable quad)
    float4 m1 = (!EDGE_LEFT  || col >= 4)        ? *reinterpret_cast<const float4*>(p - 4) : Z;
    float4 m0 =                                    *reinterpret_cast<const float4*>(p);
    float4 p1 = (!EDGE_RIGHT || col < LVAL - 4)  ? *reinterpret_cast<const float4*>(p + 4) : Z;
    float4 p2 = (!EDGE_RIGHT || col < LVAL - 8)  ? *reinterpret_cast<const float4*>(p + 8) : Z;

    // v[t] = x[row, col-4+t], t = 0..15
    float v[16] = {m1.x, m1.y, m1.z, m1.w,  m0.x, m0.y, m0.z, m0.w,
                   p1.x, p1.y, p1.z, p1.w,  p2.x, p2.y, p2.z, p2.w};

    // a_i = out[col+2+i] = sum_j kern[j] * v[i+j]
    float a0 = 0.f, a1 = 0.f, a2 = 0.f, a3 = 0.f;
    #pragma unroll
    for (int j = 0; j < TAPS; j++) {
        float kj = kern[j];
        a0 = fmaf(kj, v[j + 0], a0);
        a1 = fmaf(kj, v[j + 1], a1);
        a2 = fmaf(kj, v[j + 2], a2);
        a3 = fmaf(kj, v[j + 3], a3);
    }

    // Lane 0 of each 128-col chunk self-computes outputs col, col+1
    // (its left neighbor lives in the previous warp).
    float e0 = 0.f, e1 = 0.f;
    if (lane == 0) {
        float m2z = 0.f, m2w = 0.f;   // cols col-6, col-5
        if (!EDGE_LEFT || col >= 8) {
            float2 t = *reinterpret_cast<const float2*>(p - 6);  // 8B-aligned
            m2z = t.x; m2w = t.y;
        }
        float u[14] = {m2z, m2w, m1.x, m1.y, m1.z, m1.w,
                       m0.x, m0.y, m0.z, m0.w, p1.x, p1.y, p1.z, p1.w};
        #pragma unroll
        for (int j = 0; j < TAPS; j++) {
            e0 = fmaf(kern[j], u[j + 0], e0);
            e1 = fmaf(kern[j], u[j + 1], e1);
        }
    }

    // outputs col, col+1 come from lane-1's a2,a3 (or lane0's self-computed pair)
    float sa = __shfl_up_sync(FULL, a2, 1);
    float sb = __shfl_up_sync(FULL, a3, 1);
    if (lane == 0) { sa = e0; sb = e1; }

    *reinterpret_cast<float4*>(out + rowBase + col) = make_float4(sa, sb, a0, a1);
}

__global__ __launch_bounds__(THREADS)
void dwconv13_kernel(const float* __restrict__ x,
                     const float* __restrict__ w,
                     float* __restrict__ out)
{
    const int g    = blockIdx.x * THREADS + threadIdx.x;
    const int lane = threadIdx.x & 31;
    const long long rowBase = (long long)(g >> 9) * LVAL;   // 512 threads per row
    const int colA = (g & 511) * 4;                         // 0..2044, chunk-aligned lanes

    // Taps, flipped: kern[j] = w[6-j] (j<7), w[j] (j>=7)
    float4 w0 = *reinterpret_cast<const float4*>(w + 0);
    float4 w1 = *reinterpret_cast<const float4*>(w + 4);
    float4 w2 = *reinterpret_cast<const float4*>(w + 8);
    float  w12 = __ldg(w + 12);
    float kern[TAPS] = {w1.z, w1.y, w1.x, w0.w, w0.z, w0.y, w0.x,
                        w1.w, w2.x, w2.y, w2.z, w2.w, w12};

    // Quad A: cols 0..2047 of the row (left row-edge possible, right impossible)
    do_quad<true, false>(x, out, rowBase, colA, lane, kern);
    // Quad B: cols 2048..4095 (left impossible, right row-edge possible)
    do_quad<false, true>(x, out, rowBase, colA + 2048, lane, kern);
}

extern "C" void kernel_launch(void* const* d_in, const int* in_sizes, int n_in,
                              void* d_out, int out_size)
{
    const float* x = (const float*)d_in[0];
    const float* w = (const float*)d_in[1];
    float* out     = (float*)d_out;

    const int n = in_sizes[0];                 // 16384 * 4096
    const int nThreadsTotal = n / 8;           // 8 outputs per thread (2 quads)
    dwconv13_kernel<<<nThreadsTotal / THREADS, THREADS>>>(x, w, out);
}